// round 14
// baseline (speedup 1.0000x reference)
#include <cuda_runtime.h>
#include <stdint.h>

// GINEConv: out[n] = (1+eps)*node_feat[n] + sum_{e: dst[e]==n} relu(node_feat[src[e]] + edge_feat[e])
// N=50000, E=1600000, D=32 (f32). Indices int32.
//
// Single-pass vector-atomic design at the LTS floor (~49us of L2 traffic).
// R14: persistent grid-stride k_edge (148*4 CTAs) — removes the 12,500
// one-shot-CTA pipeline-drain bubbles; unroll-2 grid-stride loop keeps two
// iterations' independent loads in flight continuously.

#define DF 32

__global__ void k_init(const float4* __restrict__ node_feat,
                       const float* __restrict__ eps,
                       float4* __restrict__ out,
                       int n4) {
    int i = blockIdx.x * blockDim.x + threadIdx.x;
    if (i >= n4) return;
    float k = 1.0f + eps[0];
    float4 v = node_feat[i];      // also pre-warms L2 for k_edge's gathers
    out[i] = make_float4(k * v.x, k * v.y, k * v.z, k * v.w);
}

// Persistent warps: each warp processes 16-edge chunks at stride nwarps*16.
// lane = g*8 + f; thread owns edges chunk_base + g + 4u, u=0..3 (strided
// ownership, coalesced index loads). All loads front-batched per chunk;
// REDs fire-and-forget; consecutive chunks overlap in the load queue.
__global__ void __launch_bounds__(256, 4)
k_edge(const float4* __restrict__ node_feat,
       const float4* __restrict__ edge_feat,
       const int* __restrict__ src,
       const int* __restrict__ dst,
       float4* __restrict__ out,
       int E) {
    int warp   = (blockIdx.x * blockDim.x + threadIdx.x) >> 5;
    int nwarps = (gridDim.x * blockDim.x) >> 5;
    int lane = threadIdx.x & 31;
    int f = lane & 7;
    int g = lane >> 3;

    int nchunks = (E + 15) >> 4;          // 16 edges per chunk

    #pragma unroll 2
    for (int c = warp; c < nchunks; c += nwarps) {
        int base = c * 16 + g;

        int ec[4];
        bool has[4];
        #pragma unroll
        for (int u = 0; u < 4; u++) {
            int e = base + 4 * u;
            has[u] = (e < E);
            ec[u]  = has[u] ? e : 0;      // clamp keeps loads in-bounds
        }

        // ---- front-batched index loads ----
        int s[4], d[4];
        #pragma unroll
        for (int u = 0; u < 4; u++) {
            s[u] = __ldg(src + ec[u]);
            d[u] = __ldg(dst + ec[u]);
        }

        // ---- front-batched feature loads: 8 independent 16B loads ----
        float4 ef[4], nf[4];
        #pragma unroll
        for (int u = 0; u < 4; u++)
            ef[u] = __ldcs(edge_feat + (size_t)ec[u] * 8 + f);  // streaming
        #pragma unroll
        for (int u = 0; u < 4; u++)
            nf[u] = __ldg(node_feat + (size_t)s[u] * 8 + f);    // L2 gather

        // ---- compute + fire-and-forget vector reductions ----
        #pragma unroll
        for (int u = 0; u < 4; u++) {
            if (has[u]) {
                float mx = fmaxf(ef[u].x + nf[u].x, 0.f);
                float my = fmaxf(ef[u].y + nf[u].y, 0.f);
                float mz = fmaxf(ef[u].z + nf[u].z, 0.f);
                float mw = fmaxf(ef[u].w + nf[u].w, 0.f);
                float4* p = out + (size_t)d[u] * 8 + f;
                asm volatile("red.global.add.v4.f32 [%0], {%1, %2, %3, %4};"
                             :: "l"(p), "f"(mx), "f"(my), "f"(mz), "f"(mw)
                             : "memory");
            }
        }
    }
}

extern "C" void kernel_launch(void* const* d_in, const int* in_sizes, int n_in,
                              void* d_out, int out_size) {
    const float4* node_feat = (const float4*)d_in[0];  // [N, 32] f32
    const float4* edge_feat = (const float4*)d_in[1];  // [E, 32] f32
    const float*  eps       = (const float*)d_in[2];   // [1]
    const int*    src       = (const int*)d_in[3];     // [E] int32
    const int*    dst       = (const int*)d_in[4];     // [E] int32
    float4* out = (float4*)d_out;

    int N = in_sizes[0] / DF;   // 50000
    int E = in_sizes[3];        // 1600000

    // 1) residual init (same stream => ordered before the reductions)
    int n4 = N * 8;
    k_init<<<(n4 + 255) / 256, 256>>>(node_feat, eps, out, n4);

    // 2) persistent edge stream + vector-atomic scatter
    //    148 SMs * 4 CTAs/SM (matches launch_bounds residency)
    k_edge<<<148 * 4, 256>>>(node_feat, edge_feat, src, dst, out, E);
}

// round 15
// speedup vs baseline: 1.1052x; 1.1052x over previous
#include <cuda_runtime.h>
#include <stdint.h>

// GINEConv: out[n] = (1+eps)*node_feat[n] + sum_{e: dst[e]==n} relu(node_feat[src[e]] + edge_feat[e])
// N=50000, E=1600000, D=32 (f32). Indices int32.
//
// FINAL (converged) design — best measured: 49.66us total / k_edge 49.06us.
// Single pass: k_init writes the eps-residual into out, then k_edge streams
// edges and scatters each finished message row into out[dst] with
// red.global.add.v4.f32 (fire-and-forget 128-bit vector reduction).
//
// k_edge is pinned at the chip's LTS/atomic floor: ~633 MB aggregate L2
// traffic (edge stream + L2-served node gathers + RED lane traffic) at the
// ~6300 B/cyc LTS cap ≈ 49-50us. Invariant across occ 53-82%, MLP 1-4
// edges/thread, scalar/vector index loads, PDL, and persistent-CTA variants;
// degrades only when regs/occupancy drop (persistent unroll-2: 55.7us).
// This file is the best-measured configuration, locked.

#define DF 32

__global__ void k_init(const float4* __restrict__ node_feat,
                       const float* __restrict__ eps,
                       float4* __restrict__ out,
                       int n4) {
    int i = blockIdx.x * blockDim.x + threadIdx.x;
    if (i >= n4) return;
    float k = 1.0f + eps[0];
    float4 v = node_feat[i];      // also pre-warms L2 for k_edge's gathers
    out[i] = make_float4(k * v.x, k * v.y, k * v.z, k * v.w);
}

// warp = 16 edges; lane = g*8 + f (g: edge subgroup, f: float4 column).
// Thread owns edges base+g+4u, u=0..3 (strided ownership: the 4 subgroups'
// index loads coalesce). All index + feature loads front-batched before any
// compute; the four REDs are fire-and-forget.
__global__ void __launch_bounds__(256, 4)
k_edge(const float4* __restrict__ node_feat,
       const float4* __restrict__ edge_feat,
       const int* __restrict__ src,
       const int* __restrict__ dst,
       float4* __restrict__ out,
       int E) {
    int warp = (blockIdx.x * blockDim.x + threadIdx.x) >> 5;
    int lane = threadIdx.x & 31;
    int f = lane & 7;
    int g = lane >> 3;

    int base = warp * 16 + g;
    if (base >= E) return;

    int e[4], ec[4];
    bool has[4];
    #pragma unroll
    for (int u = 0; u < 4; u++) {
        e[u]   = base + 4 * u;
        has[u] = (e[u] < E);
        ec[u]  = has[u] ? e[u] : base;     // clamp keeps loads in-bounds
    }

    // ---- front-batched index loads (broadcast within 8-lane subgroup) ----
    int s[4], d[4];
    #pragma unroll
    for (int u = 0; u < 4; u++) {
        s[u] = __ldg(src + ec[u]);
        d[u] = __ldg(dst + ec[u]);
    }

    // ---- front-batched feature loads: 8 independent 16B loads ----
    float4 ef[4], nf[4];
    #pragma unroll
    for (int u = 0; u < 4; u++)
        ef[u] = __ldcs(edge_feat + (size_t)ec[u] * 8 + f);   // streaming, no reuse
    #pragma unroll
    for (int u = 0; u < 4; u++)
        nf[u] = __ldg(node_feat + (size_t)s[u] * 8 + f);     // L2-resident gather

    // ---- compute + fire-and-forget vector reductions ----
    #pragma unroll
    for (int u = 0; u < 4; u++) {
        if (has[u]) {
            float mx = fmaxf(ef[u].x + nf[u].x, 0.f);
            float my = fmaxf(ef[u].y + nf[u].y, 0.f);
            float mz = fmaxf(ef[u].z + nf[u].z, 0.f);
            float mw = fmaxf(ef[u].w + nf[u].w, 0.f);
            float4* p = out + (size_t)d[u] * 8 + f;
            asm volatile("red.global.add.v4.f32 [%0], {%1, %2, %3, %4};"
                         :: "l"(p), "f"(mx), "f"(my), "f"(mz), "f"(mw)
                         : "memory");
        }
    }
}

extern "C" void kernel_launch(void* const* d_in, const int* in_sizes, int n_in,
                              void* d_out, int out_size) {
    const float4* node_feat = (const float4*)d_in[0];  // [N, 32] f32
    const float4* edge_feat = (const float4*)d_in[1];  // [E, 32] f32
    const float*  eps       = (const float*)d_in[2];   // [1]
    const int*    src       = (const int*)d_in[3];     // [E] int32
    const int*    dst       = (const int*)d_in[4];     // [E] int32
    float4* out = (float4*)d_out;

    int N = in_sizes[0] / DF;   // 50000
    int E = in_sizes[3];        // 1600000

    // 1) residual init (same stream => ordered before the reductions)
    int n4 = N * 8;
    k_init<<<(n4 + 255) / 256, 256>>>(node_feat, eps, out, n4);

    // 2) edge stream + vector-atomic scatter, 16 edges per warp
    long long warps = ((long long)E + 15) / 16;
    long long threads = warps * 32;
    k_edge<<<(int)((threads + 255) / 256), 256>>>(node_feat, edge_feat, src, dst, out, E);
}

// round 16
// speedup vs baseline: 1.1244x; 1.0174x over previous
#include <cuda_runtime.h>
#include <stdint.h>

// GINEConv: out[n] = (1+eps)*node_feat[n] + sum_{e: dst[e]==n} relu(node_feat[src[e]] + edge_feat[e])
// N=50000, E=1600000, D=32 (f32). Indices int32.
//
// FINAL (converged, round 15) — best measured: 49.66us total / k_edge 48.86us.
// Single pass: k_init writes the eps-residual into out, then k_edge streams
// edges and scatters each finished message row into out[dst] with
// red.global.add.v4.f32 (fire-and-forget 128-bit vector reduction).
//
// k_edge sits at the chip's LTS/atomic floor: ~633 MB aggregate L2 traffic
// (edge stream + L2-served node gathers + RED lane traffic) at the ~6300 B/cyc
// LTS cap ≈ 49us. Verified invariant across occ 53-82%, MLP 1-4 edges/thread,
// scalar/vector index loads, PDL overlap, and persistent-CTA variants over
// rounds 6-15; degrades only when regs/occupancy drop. This is the
// best-measured configuration, resubmitted unchanged.

#define DF 32

__global__ void k_init(const float4* __restrict__ node_feat,
                       const float* __restrict__ eps,
                       float4* __restrict__ out,
                       int n4) {
    int i = blockIdx.x * blockDim.x + threadIdx.x;
    if (i >= n4) return;
    float k = 1.0f + eps[0];
    float4 v = node_feat[i];      // also pre-warms L2 for k_edge's gathers
    out[i] = make_float4(k * v.x, k * v.y, k * v.z, k * v.w);
}

// warp = 16 edges; lane = g*8 + f (g: edge subgroup, f: float4 column).
// Thread owns edges base+g+4u, u=0..3 (strided ownership: the 4 subgroups'
// index loads coalesce). All index + feature loads front-batched before any
// compute; the four REDs are fire-and-forget.
__global__ void __launch_bounds__(256, 4)
k_edge(const float4* __restrict__ node_feat,
       const float4* __restrict__ edge_feat,
       const int* __restrict__ src,
       const int* __restrict__ dst,
       float4* __restrict__ out,
       int E) {
    int warp = (blockIdx.x * blockDim.x + threadIdx.x) >> 5;
    int lane = threadIdx.x & 31;
    int f = lane & 7;
    int g = lane >> 3;

    int base = warp * 16 + g;
    if (base >= E) return;

    int e[4], ec[4];
    bool has[4];
    #pragma unroll
    for (int u = 0; u < 4; u++) {
        e[u]   = base + 4 * u;
        has[u] = (e[u] < E);
        ec[u]  = has[u] ? e[u] : base;     // clamp keeps loads in-bounds
    }

    // ---- front-batched index loads (broadcast within 8-lane subgroup) ----
    int s[4], d[4];
    #pragma unroll
    for (int u = 0; u < 4; u++) {
        s[u] = __ldg(src + ec[u]);
        d[u] = __ldg(dst + ec[u]);
    }

    // ---- front-batched feature loads: 8 independent 16B loads ----
    float4 ef[4], nf[4];
    #pragma unroll
    for (int u = 0; u < 4; u++)
        ef[u] = __ldcs(edge_feat + (size_t)ec[u] * 8 + f);   // streaming, no reuse
    #pragma unroll
    for (int u = 0; u < 4; u++)
        nf[u] = __ldg(node_feat + (size_t)s[u] * 8 + f);     // L2-resident gather

    // ---- compute + fire-and-forget vector reductions ----
    #pragma unroll
    for (int u = 0; u < 4; u++) {
        if (has[u]) {
            float mx = fmaxf(ef[u].x + nf[u].x, 0.f);
            float my = fmaxf(ef[u].y + nf[u].y, 0.f);
            float mz = fmaxf(ef[u].z + nf[u].z, 0.f);
            float mw = fmaxf(ef[u].w + nf[u].w, 0.f);
            float4* p = out + (size_t)d[u] * 8 + f;
            asm volatile("red.global.add.v4.f32 [%0], {%1, %2, %3, %4};"
                         :: "l"(p), "f"(mx), "f"(my), "f"(mz), "f"(mw)
                         : "memory");
        }
    }
}

extern "C" void kernel_launch(void* const* d_in, const int* in_sizes, int n_in,
                              void* d_out, int out_size) {
    const float4* node_feat = (const float4*)d_in[0];  // [N, 32] f32
    const float4* edge_feat = (const float4*)d_in[1];  // [E, 32] f32
    const float*  eps       = (const float*)d_in[2];   // [1]
    const int*    src       = (const int*)d_in[3];     // [E] int32
    const int*    dst       = (const int*)d_in[4];     // [E] int32
    float4* out = (float4*)d_out;

    int N = in_sizes[0] / DF;   // 50000
    int E = in_sizes[3];        // 1600000

    // 1) residual init (same stream => ordered before the reductions)
    int n4 = N * 8;
    k_init<<<(n4 + 255) / 256, 256>>>(node_feat, eps, out, n4);

    // 2) edge stream + vector-atomic scatter, 16 edges per warp
    long long warps = ((long long)E + 15) / 16;
    long long threads = warps * 32;
    k_edge<<<(int)((threads + 255) / 256), 256>>>(node_feat, edge_feat, src, dst, out, E);
}